// round 6
// baseline (speedup 1.0000x reference)
#include <cuda_runtime.h>

#define T_DIM 2048
#define MAX_B 8192
#define NTH   64            // threads per block == rows per block
#define ROW_W 44            // smem words per row: 16 lab + 24 out + 4 pad (16B mult)
#define FULLMASK 0xffffffffu

// Single 64-bit accumulator: bits[63:16] = biased fixed-point sum (scale 2^22,
// bias 2^38 per arriving warp), bits[15:0] = arrived-warp count. Integer adds
// are associative -> bitwise-deterministic in any arrival order. Last arriver
// holds the grand total in-hand, stores the mean, resets for the next replay.
__device__ unsigned long long g_acc = 0ULL;

__global__ __launch_bounds__(NTH)
void fused_loss_kernel(const float* __restrict__ outputs,
                       const int* __restrict__ labels,
                       float* __restrict__ out, int B) {
    __shared__ __align__(16) unsigned sm[NTH * ROW_W];   // 11.3 KB

    const int t        = threadIdx.x;
    const int blk_base = blockIdx.x * NTH;
    const int row      = blk_base + t;
    const bool full    = (blk_base + NTH <= B);

    float pf[24];
    int   la[16];

    if (full) {
        // ---- coalesced staged loads: consecutive lanes -> contiguous bytes ----
        // labels: 64 rows x 4 int4 chunks = 256 chunks, 4 passes
        const int* labB = labels + (size_t)blk_base * T_DIM;
        #pragma unroll
        for (int p = 0; p < 4; p++) {
            const int g = p * NTH + t;
            const int r = g >> 2, c = g & 3;
            int4 v = __ldg((const int4*)(labB + (size_t)r * T_DIM + c * 4));
            *(int4*)&sm[r * ROW_W + c * 4] = v;
        }
        // outputs: 64 rows x 6 float4 chunks = 384 chunks, 6 passes
        const float* outB = outputs + (size_t)blk_base * T_DIM;
        #pragma unroll
        for (int p = 0; p < 6; p++) {
            const int g = p * NTH + t;
            const int r = g / 6, c = g - r * 6;
            float4 v = __ldg((const float4*)(outB + (size_t)r * T_DIM + c * 4));
            *(float4*)&sm[r * ROW_W + 16 + c * 4] = *(float4*)&v;
        }
        __syncthreads();
        // readback own row (conflict-free within each 8-lane phase at stride 44)
        #pragma unroll
        for (int c = 0; c < 4; c++)
            *(int4*)&la[c * 4] = *(const int4*)&sm[t * ROW_W + c * 4];
        #pragma unroll
        for (int c = 0; c < 6; c++)
            *(float4*)&pf[c * 4] = *(const float4*)&sm[t * ROW_W + 16 + c * 4];
    } else if (row < B) {
        // partial tail block: direct per-thread loads
        const float* p   = outputs + (size_t)row * T_DIM;
        const int*   lab = labels  + (size_t)row * T_DIM;
        #pragma unroll
        for (int c = 0; c < 4; c++)
            *(int4*)&la[c * 4] = __ldg((const int4*)(lab + c * 4));
        #pragma unroll
        for (int c = 0; c < 6; c++)
            *(float4*)&pf[c * 4] = __ldg((const float4*)(p + c * 4));
    }

    float per = 0.0f;
    if (row < B) {
        const float* p   = outputs + (size_t)row * T_DIM;   // for tier B/C only
        const int*   lab = labels  + (size_t)row * T_DIM;

        const int lab0 = la[0];
        int ind0 = T_DIM;
        #pragma unroll
        for (int k = 15; k >= 1; k--)          // descending: smallest k wins
            if (la[k] != lab0) ind0 = k;

        if (ind0 <= 15) {
            // ---- TIER A (P ~ 1 - 2^-15): prefix + full n=8 window, regs only ----
            float S = 0.f, cp = 1.f;
            float term1 = 0.f, cpw = 1.f, cpl = 1.f, pl = 0.f;
            #pragma unroll
            for (int k = 0; k < 24; k++) {
                const float pk = pf[k];
                if (k < ind0) {                         // false-alarm prefix
                    S  += (float)(k + 1) * pk * cp;
                    cp *= 1.f - pk;
                }
                if (k >= ind0 && k < ind0 + 8) {        // delay window
                    const int kk = k - ind0;
                    term1 += (float)(kk + 1) * pk * cpw;
                    if (kk == 7) { cpl = cpw; pl = pk; }
                    cpw *= 1.f - pk;
                }
            }
            const float fa = 1.f - S;
            const float dd = term1 + 72.f * cpl * (1.f - pl);   // n=8, W+1=9
            per = 0.5f * dd + 0.5f * fa;                        // ALPHA=0.5
        } else {
            // ---- TIER B (P ~ 2^-15): one bulk parallel round trip, no chase ----
            int4   m0 = __ldg((const int4*)(lab + 16));
            int4   m1 = __ldg((const int4*)(lab + 20));
            int4   m2 = __ldg((const int4*)(lab + 24));
            int4   m3 = __ldg((const int4*)(lab + 28));
            int4   m4 = __ldg((const int4*)(lab + 32));
            int4   m5 = __ldg((const int4*)(lab + 36));
            int4   m6 = __ldg((const int4*)(lab + 40));
            int4   m7 = __ldg((const int4*)(lab + 44));
            float4 r0 = __ldg((const float4*)(p + 24));
            float4 r1 = __ldg((const float4*)(p + 28));
            float4 r2 = __ldg((const float4*)(p + 32));
            float4 r3 = __ldg((const float4*)(p + 36));
            float4 r4 = __ldg((const float4*)(p + 40));
            float4 r5 = __ldg((const float4*)(p + 44));
            float4 r6 = __ldg((const float4*)(p + 48));
            float4 r7 = __ldg((const float4*)(p + 52));

            const int   lb[32] = {m0.x,m0.y,m0.z,m0.w, m1.x,m1.y,m1.z,m1.w,
                                  m2.x,m2.y,m2.z,m2.w, m3.x,m3.y,m3.z,m3.w,
                                  m4.x,m4.y,m4.z,m4.w, m5.x,m5.y,m5.z,m5.w,
                                  m6.x,m6.y,m6.z,m6.w, m7.x,m7.y,m7.z,m7.w};
            const float pg[32] = {r0.x,r0.y,r0.z,r0.w, r1.x,r1.y,r1.z,r1.w,
                                  r2.x,r2.y,r2.z,r2.w, r3.x,r3.y,r3.z,r3.w,
                                  r4.x,r4.y,r4.z,r4.w, r5.x,r5.y,r5.z,r5.w,
                                  r6.x,r6.y,r6.z,r6.w, r7.x,r7.y,r7.z,r7.w};

            #pragma unroll
            for (int k = 31; k >= 0; k--)
                if (lb[k] != lab0) ind0 = 16 + k;

            if (ind0 <= 47) {
                float S = 0.f, cp = 1.f;
                float term1 = 0.f, cpw = 1.f, cpl = 1.f, pl = 0.f;
                #pragma unroll
                for (int k = 0; k < 56; k++) {
                    const float pk = (k < 24) ? pf[k] : pg[k - 24];
                    if (k < ind0) {
                        S  += (float)(k + 1) * pk * cp;
                        cp *= 1.f - pk;
                    }
                    if (k >= ind0 && k < ind0 + 8) {
                        const int kk = k - ind0;
                        term1 += (float)(kk + 1) * pk * cpw;
                        if (kk == 7) { cpl = cpw; pl = pk; }
                        cpw *= 1.f - pk;
                    }
                }
                const float fa = 1.f - S;
                const float dd = term1 + 72.f * cpl * (1.f - pl);
                per = 0.5f * dd + 0.5f * fa;
            } else {
                // ---- TIER C (P ~ 2^-47): fully general, correctness only ----
                ind0 = T_DIM;
                for (int base = 48; base < T_DIM; base += 4) {
                    int4 v = __ldg((const int4*)(lab + base));
                    if (v.x != lab0) { ind0 = base;     break; }
                    if (v.y != lab0) { ind0 = base + 1; break; }
                    if (v.z != lab0) { ind0 = base + 2; break; }
                    if (v.w != lab0) { ind0 = base + 3; break; }
                }
                const bool has_change = (ind0 < T_DIM);
                const int  L = has_change ? ind0 : T_DIM;
                float S = 0.f, cp = 1.f;
                for (int k = 0; k < L; k++) {
                    const float pk = p[k];
                    S  += (float)(k + 1) * pk * cp;
                    cp *= 1.f - pk;
                }
                const float fa = 1.f - S;
                if (has_change) {
                    int n = T_DIM - ind0; if (n > 8) n = 8;
                    float cpw = 1.f, term1 = 0.f, cpl = 1.f, pl = 0.f;
                    for (int kk = 0; kk < n; kk++) {
                        const float pk = p[ind0 + kk];
                        term1 += (float)(kk + 1) * pk * cpw;
                        if (kk == n - 1) { cpl = cpw; pl = pk; }
                        cpw *= 1.f - pk;
                    }
                    const float dd = term1 + (float)n * 9.f * cpl * (1.f - pl);
                    per = 0.5f * dd + 0.5f * fa;
                } else {
                    per = fa;
                }
            }
        }
    }

    // ---- warp butterfly (fixed order -> deterministic warp partial) ----
    float s = per;
    #pragma unroll
    for (int o = 16; o > 0; o >>= 1)
        s += __shfl_xor_sync(FULLMASK, s, o);

    // ---- ONE atomic per warp: sum + count packed in one 64-bit word ----
    if ((t & 31) == 0) {
        const unsigned nwarps = gridDim.x * (NTH / 32);
        long long fix = llrintf(s * 4194304.0f) + (1LL << 38);  // scale 2^22
        unsigned long long packed = ((unsigned long long)fix << 16) | 1ULL;
        unsigned long long old = atomicAdd(&g_acc, packed);
        if ((old & 0xFFFFULL) == (unsigned long long)(nwarps - 1)) {
            unsigned long long tot = old + packed;              // grand total in hand
            long long net = (long long)(tot >> 16) - ((long long)nwarps << 38);
            double sum = (double)net * (1.0 / 4194304.0);
            out[0] = (float)(sum / (double)B);
            g_acc = 0ULL;                                       // reset for replay
        }
    }
}

extern "C" void kernel_launch(void* const* d_in, const int* in_sizes, int n_in,
                              void* d_out, int out_size) {
    const float* outputs = (const float*)d_in[0];
    const int*   labels  = (const int*)d_in[1];

    int B = in_sizes[0] / T_DIM;
    if (B > MAX_B) B = MAX_B;

    int blocks = (B + NTH - 1) / NTH;     // 128 blocks -> spread over ~128 SMs
    fused_loss_kernel<<<blocks, NTH>>>(outputs, labels, (float*)d_out, B);
}